// round 2
// baseline (speedup 1.0000x reference)
#include <cuda_runtime.h>
#include <math.h>

// Problem constants
#define BN 2048
#define DN 1024
#define RN 64
#define HN 256
#define PC 256          // padded projection columns (k:0-63, v:64-127, q:128-191, logit:192)

// ---------------- device scratch (no allocations allowed) ----------------
__device__ float d_Wcat[DN * PC];
__device__ float d_bcat[PC];
__device__ float d_PROJ[BN * PC];     // k|v|q|logit per row
__device__ float d_UK[BN * HN];
__device__ float d_UQ[BN * HN];
__device__ float d_G[BN * HN];        // gelu(uk)
__device__ float d_DU[BN * HN];
__device__ float d_DO[BN * RN];
__device__ float d_ETA[BN];
__device__ float d_Z[BN * RN];

// ---------------- math helpers ----------------
__device__ __forceinline__ float gelu_f(float x) {
    const float c = 0.7978845608028654f;
    float w = c * (x + 0.044715f * x * x * x);
    float th = tanhf(w);
    return 0.5f * x * (1.f + th);
}
__device__ __forceinline__ float gelu_grad(float x) {
    const float c = 0.7978845608028654f;
    float x2 = x * x;
    float w = c * (x + 0.044715f * x2 * x);
    float th = tanhf(w);
    float sech2 = 1.f - th * th;
    return 0.5f * (1.f + th) + 0.5f * x * sech2 * c * (1.f + 3.f * 0.044715f * x2);
}

// ---------------- prep: concatenate projection weights ----------------
__global__ void prep_kernel(const float* __restrict__ Wk, const float* __restrict__ Wv,
                            const float* __restrict__ Wq, const float* __restrict__ lrw,
                            const float* __restrict__ bk, const float* __restrict__ bv,
                            const float* __restrict__ bq, const float* __restrict__ lrb) {
    int idx = blockIdx.x * blockDim.x + threadIdx.x;
    if (idx < DN * PC) {
        int d = idx >> 8;
        int c = idx & 255;
        float v = 0.f;
        if (c < 64)       v = Wk[d * 64 + c];
        else if (c < 128) v = Wv[d * 64 + (c - 64)];
        else if (c < 192) v = Wq[d * 64 + (c - 128)];
        else if (c == 192) v = lrw[d];
        d_Wcat[idx] = v;
    }
    if (blockIdx.x == 0 && threadIdx.x < PC) {
        int c = threadIdx.x;
        float v = 0.f;
        if (c < 64)       v = bk[c];
        else if (c < 128) v = bv[c - 64];
        else if (c < 192) v = bq[c - 128];
        else if (c == 192) v = lrb[0];
        d_bcat[c] = v;
    }
}

// ---------------- generic tiled SGEMM: C[64x64 tile] = A(M,K) * B(K,N) + bias ----------------
// BM=BN=64, BK=16, 256 threads, 4x4 per thread. M,N multiples of 64; K multiple of 16.
__global__ void __launch_bounds__(256)
sgemm64x64(const float* __restrict__ A, int lda,
           const float* __restrict__ Bm, int ldb,
           const float* __restrict__ bias,
           float* __restrict__ C, int ldc, int K) {
    __shared__ float As[16][64];
    __shared__ float Bs[16][64];
    int t = threadIdx.x;
    int tx = t & 15, ty = t >> 4;
    int m0 = blockIdx.y * 64, n0 = blockIdx.x * 64;
    int arow = t >> 2, aq = t & 3;     // A loader: 64 rows x 4 quads
    int brow = t >> 4, bq4 = t & 15;   // B loader: 16 rows x 16 quads
    float acc[4][4];
#pragma unroll
    for (int i = 0; i < 4; i++)
#pragma unroll
        for (int j = 0; j < 4; j++) acc[i][j] = 0.f;

    for (int k0 = 0; k0 < K; k0 += 16) {
        float4 av = *(const float4*)&A[(size_t)(m0 + arow) * lda + k0 + aq * 4];
        float4 bv = *(const float4*)&Bm[(size_t)(k0 + brow) * ldb + n0 + bq4 * 4];
        As[aq * 4 + 0][arow] = av.x;
        As[aq * 4 + 1][arow] = av.y;
        As[aq * 4 + 2][arow] = av.z;
        As[aq * 4 + 3][arow] = av.w;
        *(float4*)&Bs[brow][bq4 * 4] = bv;
        __syncthreads();
#pragma unroll
        for (int k = 0; k < 16; k++) {
            float4 a = *(float4*)&As[k][ty * 4];
            float4 b = *(float4*)&Bs[k][tx * 4];
            acc[0][0] += a.x * b.x; acc[0][1] += a.x * b.y; acc[0][2] += a.x * b.z; acc[0][3] += a.x * b.w;
            acc[1][0] += a.y * b.x; acc[1][1] += a.y * b.y; acc[1][2] += a.y * b.z; acc[1][3] += a.y * b.w;
            acc[2][0] += a.z * b.x; acc[2][1] += a.z * b.y; acc[2][2] += a.z * b.z; acc[2][3] += a.z * b.w;
            acc[3][0] += a.w * b.x; acc[3][1] += a.w * b.y; acc[3][2] += a.w * b.z; acc[3][3] += a.w * b.w;
        }
        __syncthreads();
    }
#pragma unroll
    for (int i = 0; i < 4; i++) {
        int row = m0 + ty * 4 + i;
#pragma unroll
        for (int j = 0; j < 4; j++) {
            int col = n0 + tx * 4 + j;
            float v = acc[i][j];
            if (bias) v += bias[col];
            C[(size_t)row * ldc + col] = v;
        }
    }
}

// ---------------- block-wide reduction of 3 values (256 threads) ----------------
__device__ __forceinline__ void bred3(float v1, float v2, float v3, int t,
                                      float* rsc, float* rout) {
#pragma unroll
    for (int o = 16; o > 0; o >>= 1) {
        v1 += __shfl_down_sync(0xffffffffu, v1, o);
        v2 += __shfl_down_sync(0xffffffffu, v2, o);
        v3 += __shfl_down_sync(0xffffffffu, v3, o);
    }
    if ((t & 31) == 0) {
        int w = t >> 5;
        rsc[w] = v1; rsc[8 + w] = v2; rsc[16 + w] = v3;
    }
    __syncthreads();
    if (t == 0) {
        float a = 0, b = 0, c = 0;
#pragma unroll
        for (int i = 0; i < 8; i++) { a += rsc[i]; b += rsc[8 + i]; c += rsc[16 + i]; }
        rout[0] = a; rout[1] = b; rout[2] = c;
    }
    __syncthreads();
}

// ---------------- per-sample inner pipeline ----------------
// Per sample: g=gelu(k@W1), o=g@W2, LN fwd+bwd -> do, du; eta; rank-1 corrected
// forward u2 = uq - eta(q.k)du, h2=gelu(u2), o2 = h2@W2 - eta(h2.g)do,
// z = q + LN(o2). Stores G, DU, DO, ETA, Z, loss.
__global__ void __launch_bounds__(256)
inner_kernel(const float* __restrict__ W2,
             const float* __restrict__ lng, const float* __restrict__ lnb,
             float* __restrict__ out_loss) {
    extern __shared__ float sW2[];       // 256*64 floats = 64 KB
    __shared__ float g[HN];
    __shared__ float h2[HN];
    __shared__ float part[HN];
    __shared__ float ov[RN];
    __shared__ float dov[RN];
    __shared__ float rsc[24];
    __shared__ float rout[4];

    int t = threadIdx.x;
    // load W2 to smem
    {
        const float4* w4 = (const float4*)W2;
        float4* s4 = (float4*)sW2;
        for (int i = t; i < HN * RN / 4; i += 256) s4[i] = w4[i];
    }
    float lngv = 0.f, lnbv = 0.f;
    if (t < RN) { lngv = lng[t]; lnbv = lnb[t]; }
    __syncthreads();

    const int r = t & 63, p = t >> 6;
    const int lane = t & 31;
    const float invR = 1.f / 64.f;

    for (int b = blockIdx.x; b < BN; b += gridDim.x) {
        float kf = 0.f, vf = 0.f, qf = 0.f;
        if (t < RN) {
            kf = d_PROJ[b * PC + t];
            vf = d_PROJ[b * PC + 64 + t];
            qf = d_PROJ[b * PC + 128 + t];
        }
        float ukv = d_UK[b * HN + t];
        float gv = gelu_f(ukv);
        float gpv = gelu_grad(ukv);
        g[t] = gv;
        __syncthreads();

        // o = g @ W2  (matvec, 4 partial groups of 64)
        {
            float acc = 0.f;
            const float* wp = &sW2[(p * 64) * 64 + r];
            const float* gp2 = &g[p * 64];
#pragma unroll 16
            for (int i = 0; i < 64; i++) acc += gp2[i] * wp[i * 64];
            part[t] = acc;
        }
        __syncthreads();
        float myo = 0.f, myqk = 0.f;
        if (t < RN) {
            myo = part[t] + part[64 + t] + part[128 + t] + part[192 + t];
            ov[t] = myo;
            myqk = qf * kf;
        }
        bred3(myo, myo * myo, myqk, t, rsc, rout);
        float mu = rout[0] * invR;
        float var = rout[1] * invR - mu * mu;
        float rstd = rsqrtf(var + 1e-6f);
        float qk = rout[2];

        // LN forward + loss grad
        float nh_r = 0.f, dn_r = 0.f, mydn = 0.f, myp = 0.f, mye2 = 0.f;
        if (t < RN) {
            nh_r = (ov[t] - mu) * rstd;
            float ln = nh_r * lngv + lnbv;
            float e = kf + ln - vf;
            dn_r = (2.f * invR) * e * lngv;
            mydn = dn_r;
            myp = dn_r * nh_r;
            mye2 = e * e;
        }
        bred3(mydn, myp, mye2, t, rsc, rout);
        float m1 = rout[0] * invR, m2 = rout[1] * invR, loss = rout[2] * invR;
        float eta = 0.1f / (1.f + expf(-d_PROJ[b * PC + 192]));
        if (t == 0) { out_loss[b] = loss; d_ETA[b] = eta; }
        if (t < RN) {
            float dor = rstd * (dn_r - m1 - nh_r * m2);
            dov[t] = dor;
            d_DO[b * RN + t] = dor;
        }
        __syncthreads();

        // dg = W2 @ do ; du = dg * gelu'(uk)   (rotated index avoids bank conflicts)
        float accg = 0.f;
        {
            const float* wrow = &sW2[t * 64];
#pragma unroll 16
            for (int i = 0; i < 64; i++) {
                int rr = (i + lane) & 63;
                accg += wrow[rr] * dov[rr];
            }
        }
        float du_ = accg * gpv;
        d_DU[b * HN + t] = du_;
        d_G[b * HN + t] = gv;

        // forward with updated fast weights
        float u2 = d_UQ[b * HN + t] - eta * qk * du_;
        float h2v = gelu_f(u2);
        h2[t] = h2v;
        bred3(h2v * gv, 0.f, 0.f, t, rsc, rout);
        float sgh = rout[0];

        // o2 = h2 @ W2 - eta*(h2.g)*do
        {
            float acc = 0.f;
            const float* wp = &sW2[(p * 64) * 64 + r];
            const float* hp = &h2[p * 64];
#pragma unroll 16
            for (int i = 0; i < 64; i++) acc += hp[i] * wp[i * 64];
            part[t] = acc;
        }
        __syncthreads();
        float myo2 = 0.f;
        if (t < RN) {
            myo2 = part[t] + part[64 + t] + part[128 + t] + part[192 + t] - eta * sgh * dov[t];
            ov[t] = myo2;
        }
        bred3(myo2, myo2 * myo2, 0.f, t, rsc, rout);
        float mu2 = rout[0] * invR;
        float var2 = rout[1] * invR - mu2 * mu2;
        float rstd2 = rsqrtf(var2 + 1e-6f);
        if (t < RN) {
            float nh = (ov[t] - mu2) * rstd2;
            d_Z[b * RN + t] = qf + nh * lngv + lnbv;
        }
        __syncthreads();   // protect smem before next sample
    }
}

// ---------------- W1n / W2n streaming writes (rank-1 updates) ----------------
__global__ void __launch_bounds__(256)
wupdate_kernel(const float* __restrict__ W1, const float* __restrict__ W2,
               float4* __restrict__ oW1n, float4* __restrict__ oW2n) {
    const unsigned NW1 = (unsigned)BN * 64 * 64;   // float4 count for W1n
    const unsigned TOT = 2u * NW1;
    for (unsigned idx = blockIdx.x * blockDim.x + threadIdx.x; idx < TOT;
         idx += gridDim.x * blockDim.x) {
        if (idx < NW1) {
            unsigned b = idx >> 12;
            unsigned rem = idx & 4095;
            unsigned rr = rem >> 6;
            unsigned h4 = rem & 63;
            float c = d_ETA[b] * d_PROJ[b * PC + rr];
            float4 w = ((const float4*)W1)[(rr << 6) + h4];
            float4 du = ((const float4*)d_DU)[((unsigned)b << 6) + h4];
            w.x -= c * du.x; w.y -= c * du.y; w.z -= c * du.z; w.w -= c * du.w;
            oW1n[idx] = w;
        } else {
            unsigned j = idx - NW1;
            unsigned b = j >> 12;
            unsigned rem = j & 4095;
            unsigned h = rem >> 4;
            unsigned r4 = rem & 15;
            float c = d_ETA[b] * d_G[b * HN + h];
            float4 w = ((const float4*)W2)[(h << 4) + r4];
            float4 dv = ((const float4*)d_DO)[((unsigned)b << 4) + r4];
            w.x -= c * dv.x; w.y -= c * dv.y; w.z -= c * dv.z; w.w -= c * dv.w;
            oW2n[j] = w;
        }
    }
}

// ---------------- launch ----------------
extern "C" void kernel_launch(void* const* d_in, const int* in_sizes, int n_in,
                              void* d_out, int out_size) {
    const float* x   = (const float*)d_in[0];
    const float* Wk  = (const float*)d_in[1];
    const float* bk  = (const float*)d_in[2];
    const float* Wv  = (const float*)d_in[3];
    const float* bv  = (const float*)d_in[4];
    const float* Wq  = (const float*)d_in[5];
    const float* bq  = (const float*)d_in[6];
    const float* Wo  = (const float*)d_in[7];
    const float* bo  = (const float*)d_in[8];
    const float* lng = (const float*)d_in[9];
    const float* lnb = (const float*)d_in[10];
    const float* lrw = (const float*)d_in[11];
    const float* lrb = (const float*)d_in[12];
    const float* W1  = (const float*)d_in[13];
    const float* W2  = (const float*)d_in[14];

    float* out   = (float*)d_out;                    // [2048,1024]
    float* oW1n  = out + (size_t)BN * DN;            // [2048,64,256]
    float* oW2n  = oW1n + (size_t)BN * RN * HN;      // [2048,256,64]
    float* oloss = oW2n + (size_t)BN * HN * RN;      // [2048]

    void *pWcat, *pBcat, *pPROJ, *pUK, *pUQ, *pZ;
    cudaGetSymbolAddress(&pWcat, d_Wcat);
    cudaGetSymbolAddress(&pBcat, d_bcat);
    cudaGetSymbolAddress(&pPROJ, d_PROJ);
    cudaGetSymbolAddress(&pUK, d_UK);
    cudaGetSymbolAddress(&pUQ, d_UQ);
    cudaGetSymbolAddress(&pZ, d_Z);

    // 1. build concatenated projection weights
    prep_kernel<<<DN * PC / 256, 256>>>(Wk, Wv, Wq, lrw, bk, bv, bq, lrb);

    // 2. PROJ = X @ Wcat + bcat   (M=2048, N=256, K=1024)
    sgemm64x64<<<dim3(PC / 64, BN / 64), 256>>>(x, DN, (const float*)pWcat, PC,
                                                (const float*)pBcat, (float*)pPROJ, PC, DN);

    // 3. UK = K @ W1, UQ = Q @ W1   (M=2048, N=256, K=64)
    sgemm64x64<<<dim3(HN / 64, BN / 64), 256>>>((const float*)pPROJ, PC, W1, HN,
                                                nullptr, (float*)pUK, HN, RN);
    sgemm64x64<<<dim3(HN / 64, BN / 64), 256>>>((const float*)pPROJ + 128, PC, W1, HN,
                                                nullptr, (float*)pUQ, HN, RN);

    // 4. per-sample inner pipeline
    cudaFuncSetAttribute(inner_kernel, cudaFuncAttributeMaxDynamicSharedMemorySize, 65536);
    inner_kernel<<<444, 256, 65536>>>(W2, lng, lnb, oloss);

    // 5. stream W1n / W2n
    wupdate_kernel<<<8192, 256>>>(W1, W2, (float4*)oW1n, (float4*)oW2n);

    // 6. OUT = Z @ Wo + bo   (M=2048, N=1024, K=64)
    sgemm64x64<<<dim3(DN / 64, BN / 64), 256>>>((const float*)pZ, RN, Wo, DN,
                                                bo, out, DN, RN);
}

// round 3
// speedup vs baseline: 1.0503x; 1.0503x over previous
#include <cuda_runtime.h>
#include <math.h>

#define BN 2048
#define DN 1024
#define RN 64
#define HN 256
#define PC 256          // padded projection columns (k:0-63, v:64-127, q:128-191, logit:192)

// ---------------- device scratch ----------------
__device__ float d_Wcat[DN * PC];
__device__ float d_bcat[PC];
__device__ float d_PROJ[BN * PC];
__device__ float d_Z[BN * RN];

// ---------------- math helpers ----------------
__device__ __forceinline__ float gelu_f(float x) {
    const float c = 0.7978845608028654f;
    float w = c * (x + 0.044715f * x * x * x);
    float th = tanhf(w);
    return 0.5f * x * (1.f + th);
}
__device__ __forceinline__ float gelu_grad(float x) {
    const float c = 0.7978845608028654f;
    float x2 = x * x;
    float w = c * (x + 0.044715f * x2 * x);
    float th = tanhf(w);
    float sech2 = 1.f - th * th;
    return 0.5f * (1.f + th) + 0.5f * x * sech2 * c * (1.f + 3.f * 0.044715f * x2);
}

// ---------------- prep: concatenate projection weights ----------------
__global__ void prep_kernel(const float* __restrict__ Wk, const float* __restrict__ Wv,
                            const float* __restrict__ Wq, const float* __restrict__ lrw,
                            const float* __restrict__ bk, const float* __restrict__ bv,
                            const float* __restrict__ bq, const float* __restrict__ lrb) {
    int idx = blockIdx.x * blockDim.x + threadIdx.x;
    if (idx < DN * PC) {
        int d = idx >> 8;
        int c = idx & 255;
        float v = 0.f;
        if (c < 64)       v = Wk[d * 64 + c];
        else if (c < 128) v = Wv[d * 64 + (c - 64)];
        else if (c < 192) v = Wq[d * 64 + (c - 128)];
        else if (c == 192) v = lrw[d];
        d_Wcat[idx] = v;
    }
    if (blockIdx.x == 0 && threadIdx.x < PC) {
        int c = threadIdx.x;
        float v = 0.f;
        if (c < 64)       v = bk[c];
        else if (c < 128) v = bv[c - 64];
        else if (c < 192) v = bq[c - 128];
        else if (c == 192) v = lrb[0];
        d_bcat[c] = v;
    }
}

// ---------------- proj GEMM: PROJ = X @ Wcat + bcat ----------------
// 32x64 tiles, BK=16, 256 threads, 2x4 acc, register prefetch. grid (4, 64).
__global__ void __launch_bounds__(256)
proj_gemm(const float* __restrict__ A, const float* __restrict__ Bm,
          const float* __restrict__ bias, float* __restrict__ C) {
    __shared__ float As[16 * 33];      // padded: As[k][row], stride 33
    __shared__ float Bs[16 * 64];      // Bs[k][col]
    int t = threadIdx.x;
    int tx = t & 15, ty = t >> 4;
    int m0 = blockIdx.y * 32, n0 = blockIdx.x * 64;
    int arow = t >> 2, aq = t & 3;     // t<128 loads A: 32 rows x 4 quads
    int brow = t >> 4, bq = t & 15;    // B: 16 rows x 16 quads

    float acc[2][4];
#pragma unroll
    for (int i = 0; i < 2; i++)
#pragma unroll
        for (int j = 0; j < 4; j++) acc[i][j] = 0.f;

    float4 av = make_float4(0, 0, 0, 0), bv;
    if (t < 128) av = *(const float4*)&A[(size_t)(m0 + arow) * DN + aq * 4];
    bv = *(const float4*)&Bm[(size_t)brow * PC + n0 + bq * 4];

    for (int k0 = 0; k0 < DN; k0 += 16) {
        if (t < 128) {
            As[(aq * 4 + 0) * 33 + arow] = av.x;
            As[(aq * 4 + 1) * 33 + arow] = av.y;
            As[(aq * 4 + 2) * 33 + arow] = av.z;
            As[(aq * 4 + 3) * 33 + arow] = av.w;
        }
        *(float4*)&Bs[brow * 64 + bq * 4] = bv;
        __syncthreads();
        if (k0 + 16 < DN) {
            if (t < 128) av = *(const float4*)&A[(size_t)(m0 + arow) * DN + k0 + 16 + aq * 4];
            bv = *(const float4*)&Bm[(size_t)(k0 + 16 + brow) * PC + n0 + bq * 4];
        }
#pragma unroll
        for (int k = 0; k < 16; k++) {
            float a0 = As[k * 33 + ty * 2];
            float a1 = As[k * 33 + ty * 2 + 1];
            float4 b = *(float4*)&Bs[k * 64 + tx * 4];
            acc[0][0] += a0 * b.x; acc[0][1] += a0 * b.y; acc[0][2] += a0 * b.z; acc[0][3] += a0 * b.w;
            acc[1][0] += a1 * b.x; acc[1][1] += a1 * b.y; acc[1][2] += a1 * b.z; acc[1][3] += a1 * b.w;
        }
        __syncthreads();
    }
    float4 bb = *(const float4*)&bias[n0 + tx * 4];
#pragma unroll
    for (int i = 0; i < 2; i++) {
        int row = m0 + ty * 2 + i;
        float4 v;
        v.x = acc[i][0] + bb.x; v.y = acc[i][1] + bb.y;
        v.z = acc[i][2] + bb.z; v.w = acc[i][3] + bb.w;
        *(float4*)&C[(size_t)row * PC + n0 + tx * 4] = v;
    }
}

// ---------------- generic tiled SGEMM 64x64 (for Z @ Wo) ----------------
__global__ void __launch_bounds__(256)
sgemm64x64(const float* __restrict__ A, int lda,
           const float* __restrict__ Bm, int ldb,
           const float* __restrict__ bias,
           float* __restrict__ C, int ldc, int K) {
    __shared__ float As[16][64];
    __shared__ float Bs[16][64];
    int t = threadIdx.x;
    int tx = t & 15, ty = t >> 4;
    int m0 = blockIdx.y * 64, n0 = blockIdx.x * 64;
    int arow = t >> 2, aq = t & 3;
    int brow = t >> 4, bq4 = t & 15;
    float acc[4][4];
#pragma unroll
    for (int i = 0; i < 4; i++)
#pragma unroll
        for (int j = 0; j < 4; j++) acc[i][j] = 0.f;

    for (int k0 = 0; k0 < K; k0 += 16) {
        float4 av = *(const float4*)&A[(size_t)(m0 + arow) * lda + k0 + aq * 4];
        float4 bv = *(const float4*)&Bm[(size_t)(k0 + brow) * ldb + n0 + bq4 * 4];
        As[aq * 4 + 0][arow] = av.x;
        As[aq * 4 + 1][arow] = av.y;
        As[aq * 4 + 2][arow] = av.z;
        As[aq * 4 + 3][arow] = av.w;
        *(float4*)&Bs[brow][bq4 * 4] = bv;
        __syncthreads();
#pragma unroll
        for (int k = 0; k < 16; k++) {
            float4 a = *(float4*)&As[k][ty * 4];
            float4 b = *(float4*)&Bs[k][tx * 4];
            acc[0][0] += a.x * b.x; acc[0][1] += a.x * b.y; acc[0][2] += a.x * b.z; acc[0][3] += a.x * b.w;
            acc[1][0] += a.y * b.x; acc[1][1] += a.y * b.y; acc[1][2] += a.y * b.z; acc[1][3] += a.y * b.w;
            acc[2][0] += a.z * b.x; acc[2][1] += a.z * b.y; acc[2][2] += a.z * b.z; acc[2][3] += a.z * b.w;
            acc[3][0] += a.w * b.x; acc[3][1] += a.w * b.y; acc[3][2] += a.w * b.z; acc[3][3] += a.w * b.w;
        }
        __syncthreads();
    }
#pragma unroll
    for (int i = 0; i < 4; i++) {
        int row = m0 + ty * 4 + i;
#pragma unroll
        for (int j = 0; j < 4; j++) {
            int col = n0 + tx * 4 + j;
            float v = acc[i][j];
            if (bias) v += bias[col];
            C[(size_t)row * ldc + col] = v;
        }
    }
}

// ---------------- named barrier per half (256 threads each) ----------------
__device__ __forceinline__ void barh(int half) {
    asm volatile("bar.sync %0, %1;" :: "r"(half + 3), "r"(256) : "memory");
}

// reduction of 3 values across one half (u in 0..255)
__device__ __forceinline__ void hred3(float v1, float v2, float v3, int u, int half,
                                      float* rsc, float* rout) {
#pragma unroll
    for (int o = 16; o > 0; o >>= 1) {
        v1 += __shfl_down_sync(0xffffffffu, v1, o);
        v2 += __shfl_down_sync(0xffffffffu, v2, o);
        v3 += __shfl_down_sync(0xffffffffu, v3, o);
    }
    if ((u & 31) == 0) {
        int w = u >> 5;
        rsc[w] = v1; rsc[8 + w] = v2; rsc[16 + w] = v3;
    }
    barh(half);
    if (u == 0) {
        float a = 0, b = 0, c = 0;
#pragma unroll
        for (int i = 0; i < 8; i++) { a += rsc[i]; b += rsc[8 + i]; c += rsc[16 + i]; }
        rout[0] = a; rout[1] = b; rout[2] = c;
    }
    barh(half);
}

// ---------------- mega kernel: UK/UQ + inner pipeline + W1n/W2n streaming ----------------
// 512 threads = 2 independent 256-thread halves, each processing one sample.
// W1 (64KB) + W2 (64KB) resident in smem.
#define HOFF 1280   // floats per half of per-sample scratch
__global__ void __launch_bounds__(512)
mega_kernel(const float* __restrict__ W1, const float* __restrict__ W2,
            const float* __restrict__ lng, const float* __restrict__ lnb,
            float* __restrict__ oW1n, float* __restrict__ oW2n,
            float* __restrict__ oloss) {
    extern __shared__ float sm[];
    float* sW1 = sm;                   // [64][256]
    float* sW2 = sm + 64 * 256;        // [256][64]
    __shared__ float rscS[2][24];
    __shared__ float routS[2][4];

    int t = threadIdx.x;
    int half = t >> 8;
    int u = t & 255;
    int lane = t & 31;

    float* dyn = sm + 2 * 64 * 256 + half * HOFF;
    float* kS   = dyn;          // 64
    float* qS   = dyn + 64;     // 64
    float* gS   = dyn + 128;    // 256
    float* duS  = dyn + 384;    // 256
    float* h2S  = dyn + 640;    // 256
    float* partS= dyn + 896;    // 256
    float* ovS  = dyn + 1152;   // 64
    float* dovS = dyn + 1216;   // 64
    float* rsc  = rscS[half];
    float* rout = routS[half];

    // load W1, W2 into smem (all 512 threads)
    {
        const float4* w14 = (const float4*)W1;
        const float4* w24 = (const float4*)W2;
        float4* s14 = (float4*)sW1;
        float4* s24 = (float4*)sW2;
        for (int i = t; i < 64 * 256 / 4; i += 512) { s14[i] = w14[i]; s24[i] = w24[i]; }
    }
    __syncthreads();

    float lngv = 0.f, lnbv = 0.f;
    if (u < 64) { lngv = lng[u]; lnbv = lnb[u]; }
    const float invR = 1.f / 64.f;
    const int p = u >> 6, rr = u & 63;
    const float4* s14 = (const float4*)sW1;
    const float4* s24 = (const float4*)sW2;
    const float4* du4p = (const float4*)duS;
    const float4* dov4p = (const float4*)dovS;

    for (int bp = blockIdx.x; bp < BN / 2; bp += gridDim.x) {
        int b = bp * 2 + half;
        const float* pj = d_PROJ + b * PC;
        float kf = 0.f, vf = 0.f, qf = 0.f;
        if (u < 64) {
            kf = pj[u]; vf = pj[64 + u]; qf = pj[128 + u];
            kS[u] = kf; qS[u] = qf;
        }
        float eta = 0.1f / (1.f + expf(-pj[192]));
        barh(half);

        // uk/uq = k/q @ W1  (thread u = column h)
        float uk = 0.f, uq = 0.f;
#pragma unroll 16
        for (int r = 0; r < 64; r++) {
            float w = sW1[r * 256 + u];
            uk += kS[r] * w;
            uq += qS[r] * w;
        }
        float gv = gelu_f(uk);
        float gpv = gelu_grad(uk);
        gS[u] = gv;
        barh(half);

        // o = g @ W2 partials
        {
            float acc = 0.f;
            const float* wp = &sW2[(p * 64) * 64 + rr];
            const float* gp2 = &gS[p * 64];
#pragma unroll 16
            for (int i = 0; i < 64; i++) acc += gp2[i] * wp[i * 64];
            partS[u] = acc;
        }
        barh(half);
        float myo = 0.f, myqk = (u < 64) ? qf * kf : 0.f;
        if (u < 64) {
            myo = partS[u] + partS[64 + u] + partS[128 + u] + partS[192 + u];
            ovS[u] = myo;
        }
        hred3(myo, myo * myo, myqk, u, half, rsc, rout);
        float mu = rout[0] * invR;
        float var = rout[1] * invR - mu * mu;
        float rstd = rsqrtf(var + 1e-6f);
        float qk = rout[2];

        // LN forward + loss grad
        float nh_r = 0.f, dn_r = 0.f, mydn = 0.f, myp = 0.f, mye2 = 0.f;
        if (u < 64) {
            nh_r = (ovS[u] - mu) * rstd;
            float ln = nh_r * lngv + lnbv;
            float e = kf + ln - vf;
            dn_r = (2.f * invR) * e * lngv;
            mydn = dn_r;
            myp = dn_r * nh_r;
            mye2 = e * e;
        }
        hred3(mydn, myp, mye2, u, half, rsc, rout);
        float m1 = rout[0] * invR, m2 = rout[1] * invR;
        if (u == 0) oloss[b] = rout[2] * invR;
        if (u < 64) dovS[u] = rstd * (dn_r - m1 - nh_r * m2);
        barh(half);

        // dg = W2 @ do ; du = dg * gelu'(uk)  (rotated index, conflict-free)
        float accg = 0.f;
        {
            const float* wrow = &sW2[u * 64];
#pragma unroll 16
            for (int i = 0; i < 64; i++) {
                int r2 = (i + lane) & 63;
                accg += wrow[r2] * dovS[r2];
            }
        }
        float du_ = accg * gpv;
        duS[u] = du_;

        // corrected forward
        float u2 = uq - eta * qk * du_;
        float h2v = gelu_f(u2);
        h2S[u] = h2v;
        hred3(h2v * gv, 0.f, 0.f, u, half, rsc, rout);   // bar inside also publishes duS/h2S
        float sgh = rout[0];

        // o2 = h2 @ W2 partials
        {
            float acc = 0.f;
            const float* wp = &sW2[(p * 64) * 64 + rr];
            const float* hp = &h2S[p * 64];
#pragma unroll 16
            for (int i = 0; i < 64; i++) acc += hp[i] * wp[i * 64];
            partS[u] = acc;
        }
        barh(half);
        float myo2 = 0.f;
        if (u < 64) {
            myo2 = partS[u] + partS[64 + u] + partS[128 + u] + partS[192 + u] - eta * sgh * dovS[u];
            ovS[u] = myo2;
        }
        hred3(myo2, myo2 * myo2, 0.f, u, half, rsc, rout);
        float mu2 = rout[0] * invR;
        float rstd2 = rsqrtf(rout[1] * invR - mu2 * mu2 + 1e-6f);
        if (u < 64) {
            float nh = (ovS[u] - mu2) * rstd2;
            d_Z[b * RN + u] = qf + nh * lngv + lnbv;
        }

        // ---- stream W1n, W2n (fully coalesced flat float4) ----
        float4* o1 = (float4*)oW1n + (size_t)b * 4096;
        float4* o2 = (float4*)oW2n + (size_t)b * 4096;
#pragma unroll
        for (int j = 0; j < 16; j++) {
            int idx = j * 256 + u;
            int r = idx >> 6, h4 = idx & 63;
            float c = eta * kS[r];
            float4 w = s14[idx];
            float4 d = du4p[h4];
            w.x -= c * d.x; w.y -= c * d.y; w.z -= c * d.z; w.w -= c * d.w;
            o1[idx] = w;
        }
#pragma unroll
        for (int j = 0; j < 16; j++) {
            int idx = j * 256 + u;
            int h = idx >> 4, r4 = idx & 15;
            float c = eta * gS[h];
            float4 w = s24[idx];
            float4 d = dov4p[r4];
            w.x -= c * d.x; w.y -= c * d.y; w.z -= c * d.z; w.w -= c * d.w;
            o2[idx] = w;
        }
        barh(half);   // protect per-half scratch before next sample
    }
}

// ---------------- launch ----------------
extern "C" void kernel_launch(void* const* d_in, const int* in_sizes, int n_in,
                              void* d_out, int out_size) {
    const float* x   = (const float*)d_in[0];
    const float* Wk  = (const float*)d_in[1];
    const float* bk  = (const float*)d_in[2];
    const float* Wv  = (const float*)d_in[3];
    const float* bv  = (const float*)d_in[4];
    const float* Wq  = (const float*)d_in[5];
    const float* bq  = (const float*)d_in[6];
    const float* Wo  = (const float*)d_in[7];
    const float* bo  = (const float*)d_in[8];
    const float* lng = (const float*)d_in[9];
    const float* lnb = (const float*)d_in[10];
    const float* lrw = (const float*)d_in[11];
    const float* lrb = (const float*)d_in[12];
    const float* W1  = (const float*)d_in[13];
    const float* W2  = (const float*)d_in[14];

    float* out   = (float*)d_out;                    // [2048,1024]
    float* oW1n  = out + (size_t)BN * DN;            // [2048,64,256]
    float* oW2n  = oW1n + (size_t)BN * RN * HN;      // [2048,256,64]
    float* oloss = oW2n + (size_t)BN * HN * RN;      // [2048]

    void *pWcat, *pBcat, *pPROJ, *pZ;
    cudaGetSymbolAddress(&pWcat, d_Wcat);
    cudaGetSymbolAddress(&pBcat, d_bcat);
    cudaGetSymbolAddress(&pPROJ, d_PROJ);
    cudaGetSymbolAddress(&pZ, d_Z);

    // 1. concat projection weights
    prep_kernel<<<DN * PC / 256, 256>>>(Wk, Wv, Wq, lrw, bk, bv, bq, lrb);

    // 2. PROJ = X @ Wcat + bcat   (2048 x 256 x 1024), 32x64 tiles
    proj_gemm<<<dim3(PC / 64, BN / 32), 256>>>(x, (const float*)pWcat,
                                               (const float*)pBcat, (float*)pPROJ);

    // 3. fused inner pipeline + W1n/W2n streaming
    {
        int smem = (2 * 64 * 256 + 2 * HOFF) * 4;   // 141312 bytes
        cudaFuncSetAttribute(mega_kernel, cudaFuncAttributeMaxDynamicSharedMemorySize, smem);
        mega_kernel<<<148, 512, smem>>>(W1, W2, lng, lnb, oW1n, oW2n, oloss);
    }

    // 4. OUT = Z @ Wo + bo   (2048 x 1024 x 64)
    sgemm64x64<<<dim3(DN / 64, BN / 64), 256>>>((const float*)pZ, RN, Wo, DN,
                                                bo, out, DN, RN);
}

// round 5
// speedup vs baseline: 1.1137x; 1.0604x over previous
#include <cuda_runtime.h>
#include <math.h>

#define BN 2048
#define DN 1024
#define RN 64
#define HN 256
#define PC 256          // padded projection columns (k:0-63, v:64-127, q:128-191, logit:192)
#define MWARPS 14       // warps per mega block (one sample per warp)

// ---------------- device scratch ----------------
__device__ float d_Wcat[DN * PC];
__device__ float d_bcat[PC];
__device__ float d_PROJ[BN * PC];
__device__ float d_Z[BN * RN];

// ---------------- math helpers ----------------
__device__ __forceinline__ float gelu_f(float x) {
    const float c = 0.7978845608028654f;
    float w = c * (x + 0.044715f * x * x * x);
    float th = tanhf(w);
    return 0.5f * x * (1.f + th);
}
__device__ __forceinline__ float gelu_grad(float x) {
    const float c = 0.7978845608028654f;
    float x2 = x * x;
    float w = c * (x + 0.044715f * x2 * x);
    float th = tanhf(w);
    float sech2 = 1.f - th * th;
    return 0.5f * (1.f + th) + 0.5f * x * sech2 * c * (1.f + 3.f * 0.044715f * x2);
}
__device__ __forceinline__ float wsum(float v) {
#pragma unroll
    for (int o = 16; o > 0; o >>= 1) v += __shfl_xor_sync(0xffffffffu, v, o);
    return v;
}

// ---------------- prep: concatenate projection weights ----------------
__global__ void prep_kernel(const float* __restrict__ Wk, const float* __restrict__ Wv,
                            const float* __restrict__ Wq, const float* __restrict__ lrw,
                            const float* __restrict__ bk, const float* __restrict__ bv,
                            const float* __restrict__ bq, const float* __restrict__ lrb) {
    int idx = blockIdx.x * blockDim.x + threadIdx.x;
    if (idx < DN * PC) {
        int d = idx >> 8;
        int c = idx & 255;
        float v = 0.f;
        if (c < 64)       v = Wk[d * 64 + c];
        else if (c < 128) v = Wv[d * 64 + (c - 64)];
        else if (c < 192) v = Wq[d * 64 + (c - 128)];
        else if (c == 192) v = lrw[d];
        d_Wcat[idx] = v;
    }
    if (blockIdx.x == 0 && threadIdx.x < PC) {
        int c = threadIdx.x;
        float v = 0.f;
        if (c < 64)       v = bk[c];
        else if (c < 128) v = bv[c - 64];
        else if (c < 192) v = bq[c - 128];
        else if (c == 192) v = lrb[0];
        d_bcat[c] = v;
    }
}

// ---------------- proj GEMM: PROJ = X @ Wcat + bcat (2048x256x1024) ----------------
__global__ void __launch_bounds__(256)
proj_gemm(const float* __restrict__ A, const float* __restrict__ Bm,
          const float* __restrict__ bias, float* __restrict__ C) {
    __shared__ float As[16 * 33];
    __shared__ float Bs[16 * 64];
    int t = threadIdx.x;
    int tx = t & 15, ty = t >> 4;
    int m0 = blockIdx.y * 32, n0 = blockIdx.x * 64;
    int arow = t >> 2, aq = t & 3;
    int brow = t >> 4, bq = t & 15;

    float acc[2][4];
#pragma unroll
    for (int i = 0; i < 2; i++)
#pragma unroll
        for (int j = 0; j < 4; j++) acc[i][j] = 0.f;

    float4 av = make_float4(0, 0, 0, 0), bv;
    if (t < 128) av = *(const float4*)&A[(size_t)(m0 + arow) * DN + aq * 4];
    bv = *(const float4*)&Bm[(size_t)brow * PC + n0 + bq * 4];

    for (int k0 = 0; k0 < DN; k0 += 16) {
        if (t < 128) {
            As[(aq * 4 + 0) * 33 + arow] = av.x;
            As[(aq * 4 + 1) * 33 + arow] = av.y;
            As[(aq * 4 + 2) * 33 + arow] = av.z;
            As[(aq * 4 + 3) * 33 + arow] = av.w;
        }
        *(float4*)&Bs[brow * 64 + bq * 4] = bv;
        __syncthreads();
        if (k0 + 16 < DN) {
            if (t < 128) av = *(const float4*)&A[(size_t)(m0 + arow) * DN + k0 + 16 + aq * 4];
            bv = *(const float4*)&Bm[(size_t)(k0 + 16 + brow) * PC + n0 + bq * 4];
        }
#pragma unroll
        for (int k = 0; k < 16; k++) {
            float a0 = As[k * 33 + ty * 2];
            float a1 = As[k * 33 + ty * 2 + 1];
            float4 b = *(float4*)&Bs[k * 64 + tx * 4];
            acc[0][0] += a0 * b.x; acc[0][1] += a0 * b.y; acc[0][2] += a0 * b.z; acc[0][3] += a0 * b.w;
            acc[1][0] += a1 * b.x; acc[1][1] += a1 * b.y; acc[1][2] += a1 * b.z; acc[1][3] += a1 * b.w;
        }
        __syncthreads();
    }
    float4 bb = *(const float4*)&bias[n0 + tx * 4];
#pragma unroll
    for (int i = 0; i < 2; i++) {
        int row = m0 + ty * 2 + i;
        float4 v;
        v.x = acc[i][0] + bb.x; v.y = acc[i][1] + bb.y;
        v.z = acc[i][2] + bb.z; v.w = acc[i][3] + bb.w;
        *(float4*)&C[(size_t)row * PC + n0 + tx * 4] = v;
    }
}

// ---------------- Zo GEMM: OUT = Z @ Wo + bo  (2048x1024x64, single K slab) ----------------
// 64x128 tiles, 256 threads (8x32), each 8x4 outputs, cols tx + 32*j.
// Dynamic smem: AsT 64*65 floats + Bs 64*128 floats = 49408 bytes.
__global__ void __launch_bounds__(256)
zo_gemm(const float* __restrict__ Z, const float* __restrict__ Wo,
        const float* __restrict__ bo, float* __restrict__ C) {
    extern __shared__ float zsm[];
    float* AsT = zsm;                 // AsT[k*65 + m], 4160 floats
    float* Bs  = zsm + 64 * 65;       // Bs[k*128 + n], 8192 floats
    int t = threadIdx.x;
    int tx = t & 31, ty = t >> 5;     // ty 0..7: rows ty*8..+7
    int m0 = blockIdx.y * 64, n0 = blockIdx.x * 128;

    // load Z tile transposed (coalesced global reads)
    for (int i = t; i < 64 * 64; i += 256) {
        int m = i >> 6, k = i & 63;
        AsT[k * 65 + m] = Z[(size_t)(m0 + m) * RN + k];
    }
    // load Wo tile as float4
    {
        const float4* w4 = (const float4*)Wo;
        float4* b4 = (float4*)Bs;
        for (int i4 = t; i4 < 64 * 32; i4 += 256) {
            int k = i4 >> 5, n4 = i4 & 31;
            b4[k * 32 + n4] = w4[(size_t)k * (DN / 4) + (n0 >> 2) + n4];
        }
    }
    __syncthreads();

    float acc[8][4];
#pragma unroll
    for (int i = 0; i < 8; i++)
#pragma unroll
        for (int j = 0; j < 4; j++) acc[i][j] = 0.f;

#pragma unroll 8
    for (int k = 0; k < 64; k++) {
        float a[8], bb[4];
#pragma unroll
        for (int i = 0; i < 8; i++) a[i] = AsT[k * 65 + ty * 8 + i];
#pragma unroll
        for (int j = 0; j < 4; j++) bb[j] = Bs[k * 128 + tx + 32 * j];
#pragma unroll
        for (int i = 0; i < 8; i++)
#pragma unroll
            for (int j = 0; j < 4; j++) acc[i][j] += a[i] * bb[j];
    }

    float bias[4];
#pragma unroll
    for (int j = 0; j < 4; j++) bias[j] = bo[n0 + tx + 32 * j];
#pragma unroll
    for (int i = 0; i < 8; i++) {
        int row = m0 + ty * 8 + i;
#pragma unroll
        for (int j = 0; j < 4; j++)
            C[(size_t)row * DN + n0 + tx + 32 * j] = acc[i][j] + bias[j];
    }
}

// ---------------- mega kernel: warp-per-sample inner pipeline + W streaming ----------------
// Lane l owns r in {l, 32+l} and h in {l+32j, j=0..7}.
// sW1: [64][256] unpadded. sW2p: [256] rows, stride 65 (conflict-free both ways).
__global__ void __launch_bounds__(MWARPS * 32)
mega_kernel(const float* __restrict__ W1, const float* __restrict__ W2,
            const float* __restrict__ lng, const float* __restrict__ lnb,
            float* __restrict__ oW1n, float* __restrict__ oW2n,
            float* __restrict__ oloss) {
    extern __shared__ float sm[];
    float* sW1  = sm;                         // 16384
    float* sW2p = sm + 16384;                 // 256*65 = 16640

    int t = threadIdx.x;
    int wid = t >> 5;
    int l = t & 31;

    // cooperative load of W1 (float4) and W2 (scalar into padded layout)
    {
        const float4* w14 = (const float4*)W1;
        float4* s14 = (float4*)sW1;
        for (int i = t; i < 64 * 256 / 4; i += MWARPS * 32) s14[i] = w14[i];
        for (int i = t; i < 256 * 64; i += MWARPS * 32) {
            int h = i >> 6, r = i & 63;
            sW2p[h * 65 + r] = W2[i];
        }
    }
    __syncthreads();

    int b = blockIdx.x * MWARPS + wid;
    if (b >= BN) return;

    float* wscr = sm + 33024 + wid * 960;
    float2* kqS = (float2*)wscr;              // 64 float2
    float* gS   = wscr + 128;                 // 256
    float* duS  = wscr + 384;                 // 256
    float* h2S  = wscr + 640;                 // 256
    float* dovS = wscr + 896;                 // 64

    const float invR = 1.f / 64.f;
    const float* pj = d_PROJ + b * PC;

    // per-lane r values
    float kf0 = pj[l],        kf1 = pj[32 + l];
    float vf0 = pj[64 + l],   vf1 = pj[96 + l];
    float qf0 = pj[128 + l],  qf1 = pj[160 + l];
    float eta = 0.1f / (1.f + expf(-pj[192]));
    float lng0 = lng[l], lng1 = lng[32 + l];
    float lnb0 = lnb[l], lnb1 = lnb[32 + l];

    kqS[l]      = make_float2(kf0, qf0);
    kqS[32 + l] = make_float2(kf1, qf1);
    __syncwarp();

    // ---- uk/uq = k/q @ W1 ---- (h = l + 32*j)
    float uk[8], uq[8];
#pragma unroll
    for (int j = 0; j < 8; j++) { uk[j] = 0.f; uq[j] = 0.f; }
#pragma unroll 8
    for (int r = 0; r < 64; r++) {
        float2 kq = kqS[r];
        const float* wrow = &sW1[r * 256 + l];
#pragma unroll
        for (int j = 0; j < 8; j++) {
            float w = wrow[32 * j];
            uk[j] += kq.x * w;
            uq[j] += kq.y * w;
        }
    }
    float gv[8], gp[8];
#pragma unroll
    for (int j = 0; j < 8; j++) {
        gv[j] = gelu_f(uk[j]);
        gp[j] = gelu_grad(uk[j]);
        gS[l + 32 * j] = gv[j];
    }
    __syncwarp();

    // ---- o = g @ W2 ---- (lane owns r = l, 32+l)
    float o0 = 0.f, o1 = 0.f;
#pragma unroll 8
    for (int h = 0; h < 256; h++) {
        float gh = gS[h];
        const float* wrow = &sW2p[h * 65 + l];
        o0 += gh * wrow[0];
        o1 += gh * wrow[32];
    }
    float s1 = wsum(o0 + o1);
    float s2 = wsum(o0 * o0 + o1 * o1);
    float qk = wsum(qf0 * kf0 + qf1 * kf1);
    float mu = s1 * invR;
    float var = s2 * invR - mu * mu;
    float rstd = rsqrtf(var + 1e-6f);

    // ---- LN forward + loss grad ----
    float nh0 = (o0 - mu) * rstd, nh1 = (o1 - mu) * rstd;
    float e0 = kf0 + nh0 * lng0 + lnb0 - vf0;
    float e1 = kf1 + nh1 * lng1 + lnb1 - vf1;
    float dn0 = (2.f * invR) * e0 * lng0;
    float dn1 = (2.f * invR) * e1 * lng1;
    float m1 = wsum(dn0 + dn1) * invR;
    float m2 = wsum(dn0 * nh0 + dn1 * nh1) * invR;
    float loss = wsum(e0 * e0 + e1 * e1) * invR;
    float dov0 = rstd * (dn0 - m1 - nh0 * m2);
    float dov1 = rstd * (dn1 - m1 - nh1 * m2);
    dovS[l] = dov0;
    dovS[32 + l] = dov1;
    if (l == 0) oloss[b] = loss;
    __syncwarp();

    // ---- dg = W2 @ dov ; du = dg * gelu'(uk) ----
    float dg[8];
#pragma unroll
    for (int j = 0; j < 8; j++) dg[j] = 0.f;
#pragma unroll 8
    for (int r = 0; r < 64; r++) {
        float dr = dovS[r];
        const float* wcol = &sW2p[l * 65 + r];     // row l+32j => offset (l+32j)*65
#pragma unroll
        for (int j = 0; j < 8; j++) dg[j] += wcol[j * 2080] * dr;   // 32*65 = 2080
    }
    float sgh_p = 0.f;
    float du[8], h2[8];
#pragma unroll
    for (int j = 0; j < 8; j++) {
        du[j] = dg[j] * gp[j];
        duS[l + 32 * j] = du[j];
        float u2 = uq[j] - eta * qk * du[j];
        h2[j] = gelu_f(u2);
        h2S[l + 32 * j] = h2[j];
        sgh_p += h2[j] * gv[j];
    }
    float sgh = wsum(sgh_p);
    __syncwarp();

    // ---- o2 = h2 @ W2 - eta*sgh*dov ----
    float p0 = 0.f, p1 = 0.f;
#pragma unroll 8
    for (int h = 0; h < 256; h++) {
        float hh = h2S[h];
        const float* wrow = &sW2p[h * 65 + l];
        p0 += hh * wrow[0];
        p1 += hh * wrow[32];
    }
    p0 -= eta * sgh * dov0;
    p1 -= eta * sgh * dov1;
    float t1 = wsum(p0 + p1);
    float t2 = wsum(p0 * p0 + p1 * p1);
    float mu2 = t1 * invR;
    float rstd2 = rsqrtf(t2 * invR - mu2 * mu2 + 1e-6f);
    d_Z[b * RN + l]      = qf0 + (p0 - mu2) * rstd2 * lng0 + lnb0;
    d_Z[b * RN + 32 + l] = qf1 + (p1 - mu2) * rstd2 * lng1 + lnb1;

    // ---- stream W1n = W1 - eta*k[r]*du[h]  (flat float4, coalesced) ----
    {
        const float4* s14 = (const float4*)sW1;
        const float4* du4 = (const float4*)duS;
        float4* o1p = (float4*)oW1n + (size_t)b * 4096;
#pragma unroll 4
        for (int it = 0; it < 128; it++) {
            int idx = it * 32 + l;
            int r = idx >> 6, h4 = idx & 63;
            float c = eta * kqS[r].x;
            float4 w = s14[idx];
            float4 d = du4[h4];
            w.x -= c * d.x; w.y -= c * d.y; w.z -= c * d.z; w.w -= c * d.w;
            o1p[idx] = w;
        }
    }
    // ---- stream W2n = W2 - eta*g[h]*dov[r] ----
    {
        const float4* dov4 = (const float4*)dovS;
        float4* o2p = (float4*)oW2n + (size_t)b * 4096;
#pragma unroll 4
        for (int it = 0; it < 128; it++) {
            int idx = it * 32 + l;
            int h = idx >> 4, r4 = idx & 15;
            float c = eta * gS[h];
            const float* wp = &sW2p[h * 65 + r4 * 4];
            float4 d = dov4[r4];
            float4 w;
            w.x = wp[0] - c * d.x;
            w.y = wp[1] - c * d.y;
            w.z = wp[2] - c * d.z;
            w.w = wp[3] - c * d.w;
            o2p[idx] = w;
        }
    }
}

// ---------------- launch ----------------
extern "C" void kernel_launch(void* const* d_in, const int* in_sizes, int n_in,
                              void* d_out, int out_size) {
    const float* x   = (const float*)d_in[0];
    const float* Wk  = (const float*)d_in[1];
    const float* bk  = (const float*)d_in[2];
    const float* Wv  = (const float*)d_in[3];
    const float* bv  = (const float*)d_in[4];
    const float* Wq  = (const float*)d_in[5];
    const float* bq  = (const float*)d_in[6];
    const float* Wo  = (const float*)d_in[7];
    const float* bo  = (const float*)d_in[8];
    const float* lng = (const float*)d_in[9];
    const float* lnb = (const float*)d_in[10];
    const float* lrw = (const float*)d_in[11];
    const float* lrb = (const float*)d_in[12];
    const float* W1  = (const float*)d_in[13];
    const float* W2  = (const float*)d_in[14];

    float* out   = (float*)d_out;                    // [2048,1024]
    float* oW1n  = out + (size_t)BN * DN;            // [2048,64,256]
    float* oW2n  = oW1n + (size_t)BN * RN * HN;      // [2048,256,64]
    float* oloss = oW2n + (size_t)BN * HN * RN;      // [2048]

    void *pWcat, *pBcat, *pPROJ, *pZ;
    cudaGetSymbolAddress(&pWcat, d_Wcat);
    cudaGetSymbolAddress(&pBcat, d_bcat);
    cudaGetSymbolAddress(&pPROJ, d_PROJ);
    cudaGetSymbolAddress(&pZ, d_Z);

    // 1. concat projection weights
    prep_kernel<<<DN * PC / 256, 256>>>(Wk, Wv, Wq, lrw, bk, bv, bq, lrb);

    // 2. PROJ = X @ Wcat + bcat
    proj_gemm<<<dim3(PC / 64, BN / 32), 256>>>(x, (const float*)pWcat,
                                               (const float*)pBcat, (float*)pPROJ);

    // 3. warp-per-sample inner pipeline + W1n/W2n streaming
    {
        int smem = (33024 + MWARPS * 960) * 4;      // 185,856 bytes
        cudaFuncSetAttribute(mega_kernel, cudaFuncAttributeMaxDynamicSharedMemorySize, smem);
        int blocks = (BN + MWARPS - 1) / MWARPS;    // 147
        mega_kernel<<<blocks, MWARPS * 32, smem>>>(W1, W2, lng, lnb, oW1n, oW2n, oloss);
    }

    // 4. OUT = Z @ Wo + bo  (dynamic smem: 49408 bytes)
    {
        int zsmem = (64 * 65 + 64 * 128) * 4;
        cudaFuncSetAttribute(zo_gemm, cudaFuncAttributeMaxDynamicSharedMemorySize, zsmem);
        zo_gemm<<<dim3(DN / 128, BN / 64), 256, zsmem>>>((const float*)pZ, Wo, bo, out);
    }
}